// round 7
// baseline (speedup 1.0000x reference)
#include <cuda_runtime.h>

#define TILE 128
#define NT_MAX 64
#define MAX_BLOCKS (NT_MAX * (NT_MAX + 1) / 2)   // 2080 for N=8192

// Per-block partial sums + completion counter (no allocations, deterministic).
__device__ double g_partials[MAX_BLOCKS];
__device__ int    g_count = 0;

static __device__ __forceinline__ float ex2_approx(float x) {
    float r; asm("ex2.approx.f32 %0, %1;" : "=f"(r) : "f"(x)); return r;
}
static __device__ __forceinline__ float rcp_approx(float x) {
    float r; asm("rcp.approx.f32 %0, %1;" : "=f"(r) : "f"(x)); return r;
}
static __device__ __forceinline__ float neg_abs(float x) {   // -|x| : one LOP3 (alu pipe)
    return __int_as_float(__float_as_int(x) | 0x80000000);
}

// degree-4 minimax-ish (Chebyshev c=-0.171573 expansion of ln(3+z)) for
// log1p(e), e in [0,1]; |err| <= ~7e-5
#define P_B0  0.0000655f
#define P_B1  0.9962636f
#define P_B2 -0.4664492f
#define P_B3  0.2186752f
#define P_B4 -0.0554640f

#define LOG2E 1.44269504088896340f
#define LN2   0.69314718055994531f

__global__ void __launch_bounds__(TILE)
wrnl_kernel(const float* __restrict__ logits,
            const int* __restrict__ rankings,   // JAX x64 disabled -> int32
            float* __restrict__ out,
            int n, int nt, int nblocks) {
    const int t = threadIdx.x;

    // ---- decode triangular block index k -> (ti, tj), ti <= tj ----
    const int k = blockIdx.x;
    float bb = 2.0f * (float)nt + 1.0f;
    int ti = (int)((bb - sqrtf(bb * bb - 8.0f * (float)k)) * 0.5f);
    while (ti > 0 && k < ti * nt - (ti * (ti - 1)) / 2) --ti;
    while (k >= (ti + 1) * nt - ((ti + 1) * ti) / 2) ++ti;
    const int tj = ti + (k - (ti * nt - (ti * (ti - 1)) / 2));

    // j-tile: {logit_j * log2e, rank_j as float}; LDS.64 broadcast per iteration
    __shared__ float2 sJ[TILE];

    const int gi = ti * TILE + t;
    const int gj = tj * TILE + t;

    float lip, ri;                       // li pre-scaled by log2e
    if (gi < n) { lip = logits[gi] * LOG2E; ri = (float)rankings[gi]; }
    else        { lip = 0.0f;               ri = 3.0e9f; }   // never active
    if (gj < n) sJ[t] = make_float2(logits[gj] * LOG2E, (float)rankings[gj]);
    else        sJ[t] = make_float2(0.0f, -1.0f);            // rj=-1 -> inactive
    __syncthreads();

    float acc0 = 0.0f, acc1 = 0.0f;

    if (ti != tj) {
        // off-diagonal: i<j holds globally; only the rank test gates a pair
        #pragma unroll 16
        for (int j = 0; j < TILE; ++j) {
            float2 lr = sJ[j];                    // LDS.64 broadcast
            float dp = lr.x - lip;                // d' = (lj-li)*log2e   (FADD)
            float e  = ex2_approx(neg_abs(dp));   // exp(-|d|)  (LOP3 + MUFU)
            float p  = fmaf(P_B4, e, P_B3);       // log1p(e): 4 FFMA
            p = fmaf(p, e, P_B2);
            p = fmaf(p, e, P_B1);
            p = fmaf(p, e, P_B0);
            float m  = fmaxf(dp, 0.0f);           // FMNMX (alu)
            float sp = fmaf(m, LN2, p);           // softplus (FFMA)
            float w  = rcp_approx(ri + lr.y);     // FADD + MUFU.RCP
            if (ri < lr.y) {                      // FSETP -> predicated FFMA
                if (j & 1) acc1 = fmaf(sp, w, acc1);
                else       acc0 = fmaf(sp, w, acc0);
            }
        }
    } else {
        // diagonal tile: additionally require t < j
        #pragma unroll 16
        for (int j = 0; j < TILE; ++j) {
            float2 lr = sJ[j];
            float dp = lr.x - lip;
            float e  = ex2_approx(neg_abs(dp));
            float p  = fmaf(P_B4, e, P_B3);
            p = fmaf(p, e, P_B2);
            p = fmaf(p, e, P_B1);
            p = fmaf(p, e, P_B0);
            float m  = fmaxf(dp, 0.0f);
            float sp = fmaf(m, LN2, p);
            float w  = rcp_approx(ri + lr.y);
            if ((ri < lr.y) && (t < j)) {
                if (j & 1) acc1 = fmaf(sp, w, acc1);
                else       acc0 = fmaf(sp, w, acc0);
            }
        }
    }

    // ---- block reduction to one double partial ----
    float acc = acc0 + acc1;
    #pragma unroll
    for (int off = 16; off > 0; off >>= 1)
        acc += __shfl_down_sync(0xffffffffu, acc, off);

    __shared__ float warpSum[4];
    __shared__ bool  isLast;
    if ((t & 31) == 0) warpSum[t >> 5] = acc;
    __syncthreads();
    if (t == 0) {
        double s = (double)warpSum[0] + (double)warpSum[1]
                 + (double)warpSum[2] + (double)warpSum[3];
        g_partials[k] = s;
        __threadfence();
        int old = atomicAdd(&g_count, 1);
        isLast = (old == nblocks - 1);
    }
    __syncthreads();
    if (!isLast) return;

    // ---- last block: deterministic final reduction ----
    __threadfence();
    double a = 0.0;
    for (int i = t; i < nblocks; i += TILE) a += g_partials[i];
    #pragma unroll
    for (int off = 16; off > 0; off >>= 1)
        a += __shfl_down_sync(0xffffffffu, a, off);

    __shared__ double ws2[4];
    if ((t & 31) == 0) ws2[t >> 5] = a;
    __syncthreads();
    if (t == 0) {
        double s = ws2[0] + ws2[1] + ws2[2] + ws2[3];
        out[0] = (float)(s / (double)n);
        g_count = 0;                      // reset for next graph replay
    }
}

extern "C" void kernel_launch(void* const* d_in, const int* in_sizes, int n_in,
                              void* d_out, int out_size) {
    const float* logits   = (const float*)d_in[0];
    const int*   rankings = (const int*)d_in[1];
    int n  = in_sizes[0];
    int nt = (n + TILE - 1) / TILE;          // 64 for N=8192
    int nblocks = nt * (nt + 1) / 2;         // 2080

    wrnl_kernel<<<nblocks, TILE>>>(logits, rankings, (float*)d_out, n, nt, nblocks);
}

// round 8
// speedup vs baseline: 1.1636x; 1.1636x over previous
#include <cuda_runtime.h>

#define TILE 128
#define NT_MAX 64
#define MAX_BLOCKS (NT_MAX * (NT_MAX + 1) / 2)   // 2080 for N=8192

// Per-block partial sums + completion counter (no allocations, deterministic).
__device__ double g_partials[MAX_BLOCKS];
__device__ int    g_count = 0;

static __device__ __forceinline__ float ex2_approx(float x) {
    float r; asm("ex2.approx.f32 %0, %1;" : "=f"(r) : "f"(x)); return r;
}
static __device__ __forceinline__ float lg2_approx(float x) {
    float r; asm("lg2.approx.f32 %0, %1;" : "=f"(r) : "f"(x)); return r;
}
static __device__ __forceinline__ float rcp_approx(float x) {
    float r; asm("rcp.approx.f32 %0, %1;" : "=f"(r) : "f"(x)); return r;
}

#define LOG2E 1.44269504088896340f
#define LN2_D 0.6931471805599453094  // double, applied once at the end

__global__ void __launch_bounds__(TILE)
wrnl_kernel(const float* __restrict__ logits,
            const int* __restrict__ rankings,   // JAX x64 disabled -> int32
            float* __restrict__ out,
            int n, int nt, int nblocks) {
    const int t = threadIdx.x;

    // ---- decode triangular block index k -> (ti, tj), ti <= tj ----
    const int k = blockIdx.x;
    float bb = 2.0f * (float)nt + 1.0f;
    int ti = (int)((bb - sqrtf(bb * bb - 8.0f * (float)k)) * 0.5f);
    while (ti > 0 && k < ti * nt - (ti * (ti - 1)) / 2) --ti;
    while (k >= (ti + 1) * nt - ((ti + 1) * ti) / 2) ++ti;
    const int tj = ti + (k - (ti * nt - (ti * (ti - 1)) / 2));

    // j-tile packed 2 entries per float4: {x_{2b}, r_{2b}, x_{2b+1}, r_{2b+1}}
    // where x_j = logit_j * log2e (pre-scaled), r_j = rank_j as float.
    __shared__ float4 sJ[TILE / 2];

    const int gi = ti * TILE + t;
    const int gj = tj * TILE + t;

    float lip, ri;                       // li pre-scaled by log2e
    if (gi < n) { lip = logits[gi] * LOG2E; ri = (float)rankings[gi]; }
    else        { lip = 0.0f;               ri = 3.0e9f; }   // never active
    {
        float xj, rj;
        if (gj < n) { xj = logits[gj] * LOG2E; rj = (float)rankings[gj]; }
        else        { xj = 0.0f;               rj = -1.0f; }  // inactive
        ((float2*)sJ)[t] = make_float2(xj, rj);
    }
    __syncthreads();

    float acc0 = 0.0f, acc1 = 0.0f;

    if (ti != tj) {
        // off-diagonal: i<j holds globally; only the rank test gates a pair
        #pragma unroll 16
        for (int b = 0; b < TILE / 2; ++b) {
            float4 q = sJ[b];                     // LDS.128 broadcast, 2 j's
            // pair 0
            float x0 = q.x - lip;                 // (lj-li)*log2e      FADD
            float e0 = ex2_approx(x0);            //                    MUFU
            float g0 = lg2_approx(1.0f + e0);     // FADD + MUFU
            float w0 = rcp_approx(ri + q.y);      // FADD + MUFU
            if (ri < q.y) acc0 = fmaf(g0, w0, acc0);   // FSETP + @P FFMA
            // pair 1
            float x1 = q.z - lip;
            float e1 = ex2_approx(x1);
            float g1 = lg2_approx(1.0f + e1);
            float w1 = rcp_approx(ri + q.w);
            if (ri < q.w) acc1 = fmaf(g1, w1, acc1);
        }
    } else {
        // diagonal tile: additionally require t < j (j = 2b, 2b+1)
        #pragma unroll 16
        for (int b = 0; b < TILE / 2; ++b) {
            float4 q = sJ[b];
            int jj = 2 * b;
            float x0 = q.x - lip;
            float e0 = ex2_approx(x0);
            float g0 = lg2_approx(1.0f + e0);
            float w0 = rcp_approx(ri + q.y);
            if ((ri < q.y) && (t < jj)) acc0 = fmaf(g0, w0, acc0);
            float x1 = q.z - lip;
            float e1 = ex2_approx(x1);
            float g1 = lg2_approx(1.0f + e1);
            float w1 = rcp_approx(ri + q.w);
            if ((ri < q.w) && (t < jj + 1)) acc1 = fmaf(g1, w1, acc1);
        }
    }

    // ---- block reduction to one double partial ----
    float acc = acc0 + acc1;
    #pragma unroll
    for (int off = 16; off > 0; off >>= 1)
        acc += __shfl_down_sync(0xffffffffu, acc, off);

    __shared__ float warpSum[4];
    __shared__ bool  isLast;
    if ((t & 31) == 0) warpSum[t >> 5] = acc;
    __syncthreads();
    if (t == 0) {
        double s = (double)warpSum[0] + (double)warpSum[1]
                 + (double)warpSum[2] + (double)warpSum[3];
        g_partials[k] = s;
        __threadfence();
        int old = atomicAdd(&g_count, 1);
        isLast = (old == nblocks - 1);
    }
    __syncthreads();
    if (!isLast) return;

    // ---- last block: deterministic final reduction ----
    __threadfence();
    double a = 0.0;
    for (int i = t; i < nblocks; i += TILE) a += g_partials[i];
    #pragma unroll
    for (int off = 16; off > 0; off >>= 1)
        a += __shfl_down_sync(0xffffffffu, a, off);

    __shared__ double ws2[4];
    if ((t & 31) == 0) ws2[t >> 5] = a;
    __syncthreads();
    if (t == 0) {
        double s = ws2[0] + ws2[1] + ws2[2] + ws2[3];
        out[0] = (float)(s * LN2_D / (double)n);   // ln2 hoisted out of the whole sum
        g_count = 0;                               // reset for next graph replay
    }
}

extern "C" void kernel_launch(void* const* d_in, const int* in_sizes, int n_in,
                              void* d_out, int out_size) {
    const float* logits   = (const float*)d_in[0];
    const int*   rankings = (const int*)d_in[1];
    int n  = in_sizes[0];
    int nt = (n + TILE - 1) / TILE;          // 64 for N=8192
    int nblocks = nt * (nt + 1) / 2;         // 2080

    wrnl_kernel<<<nblocks, TILE>>>(logits, rankings, (float*)d_out, n, nt, nblocks);
}

// round 9
// speedup vs baseline: 1.2515x; 1.0756x over previous
#include <cuda_runtime.h>

#define TILE 128
#define NT_MAX 64
#define MAX_BLOCKS (NT_MAX * (NT_MAX + 1) / 2)   // 2080 for N=8192

// Per-block partial sums + completion counter (no allocations, deterministic).
__device__ double g_partials[MAX_BLOCKS];
__device__ int    g_count = 0;

static __device__ __forceinline__ float ex2_approx(float x) {
    float r; asm("ex2.approx.f32 %0, %1;" : "=f"(r) : "f"(x)); return r;
}
static __device__ __forceinline__ float lg2_approx(float x) {
    float r; asm("lg2.approx.f32 %0, %1;" : "=f"(r) : "f"(x)); return r;
}
// 1/x for x in [1, ~2^15]: bit-magic seed (~5% err) + 2 Newton steps (~1e-6 err).
// 1 alu + 4 fma-pipe ops; independent of the EX2/LG2 chain (ILP).
static __device__ __forceinline__ float fast_rcp(float x) {
    float y = __int_as_float(0x7EF311C2 - __float_as_int(x));
    y = y * fmaf(-x, y, 2.0f);
    y = y * fmaf(-x, y, 2.0f);
    return y;
}

#define LOG2E 1.44269504088896340f
#define LN2_D 0.6931471805599453094  // double, applied once at the end

__global__ void __launch_bounds__(TILE)
wrnl_kernel(const float* __restrict__ logits,
            const int* __restrict__ rankings,   // JAX x64 disabled -> int32
            float* __restrict__ out,
            int n, int nt, int nblocks) {
    const int t = threadIdx.x;

    // ---- decode triangular block index k -> (ti, tj), ti <= tj ----
    const int k = blockIdx.x;
    float bb = 2.0f * (float)nt + 1.0f;
    int ti = (int)((bb - sqrtf(bb * bb - 8.0f * (float)k)) * 0.5f);
    while (ti > 0 && k < ti * nt - (ti * (ti - 1)) / 2) --ti;
    while (k >= (ti + 1) * nt - ((ti + 1) * ti) / 2) ++ti;
    const int tj = ti + (k - (ti * nt - (ti * (ti - 1)) / 2));

    // j-tile packed 2 entries per float4: {x0, r0(int bits), x1, r1(int bits)}
    // where x_j = logit_j * log2e (pre-scaled), r_j kept as int32.
    __shared__ float4 sJ[TILE / 2];

    const int gi = ti * TILE + t;
    const int gj = tj * TILE + t;

    float lip; int ri;                   // li pre-scaled by log2e; rank as int
    if (gi < n) { lip = logits[gi] * LOG2E; ri = rankings[gi]; }
    else        { lip = 0.0f;               ri = 0x40000000; } // never active, no overflow
    {
        float xj; int rj;
        if (gj < n) { xj = logits[gj] * LOG2E; rj = rankings[gj]; }
        else        { xj = 0.0f;               rj = -1; }       // ri < -1 never true
        ((float2*)sJ)[t] = make_float2(xj, __int_as_float(rj));
    }
    __syncthreads();

    float acc0 = 0.0f, acc1 = 0.0f;

    if (ti != tj) {
        // off-diagonal: i<j holds globally; only the rank test gates a pair
        #pragma unroll 16
        for (int b = 0; b < TILE / 2; ++b) {
            float4 q = sJ[b];                       // LDS.128 broadcast, 2 j's
            int rj0 = __float_as_int(q.y);
            int rj1 = __float_as_int(q.w);
            // pair 0
            float x0 = q.x - lip;                   // (lj-li)*log2e   FADD
            float e0 = ex2_approx(x0);              // MUFU.EX2
            float g0 = lg2_approx(1.0f + e0);       // FADD + MUFU.LG2
            float w0 = fast_rcp((float)(ri + rj0)); // IADD + I2F + 1 alu + 4 fma
            if (ri < rj0) acc0 = fmaf(g0, w0, acc0);// ISETP + @P FFMA
            // pair 1
            float x1 = q.z - lip;
            float e1 = ex2_approx(x1);
            float g1 = lg2_approx(1.0f + e1);
            float w1 = fast_rcp((float)(ri + rj1));
            if (ri < rj1) acc1 = fmaf(g1, w1, acc1);
        }
    } else {
        // diagonal tile: additionally require t < j (j = 2b, 2b+1)
        #pragma unroll 16
        for (int b = 0; b < TILE / 2; ++b) {
            float4 q = sJ[b];
            int rj0 = __float_as_int(q.y);
            int rj1 = __float_as_int(q.w);
            int jj = 2 * b;
            float x0 = q.x - lip;
            float e0 = ex2_approx(x0);
            float g0 = lg2_approx(1.0f + e0);
            float w0 = fast_rcp((float)(ri + rj0));
            if ((ri < rj0) && (t < jj)) acc0 = fmaf(g0, w0, acc0);
            float x1 = q.z - lip;
            float e1 = ex2_approx(x1);
            float g1 = lg2_approx(1.0f + e1);
            float w1 = fast_rcp((float)(ri + rj1));
            if ((ri < rj1) && (t < jj + 1)) acc1 = fmaf(g1, w1, acc1);
        }
    }

    // ---- block reduction to one double partial ----
    float acc = acc0 + acc1;
    #pragma unroll
    for (int off = 16; off > 0; off >>= 1)
        acc += __shfl_down_sync(0xffffffffu, acc, off);

    __shared__ float warpSum[4];
    __shared__ bool  isLast;
    if ((t & 31) == 0) warpSum[t >> 5] = acc;
    __syncthreads();
    if (t == 0) {
        double s = (double)warpSum[0] + (double)warpSum[1]
                 + (double)warpSum[2] + (double)warpSum[3];
        g_partials[k] = s;
        __threadfence();
        int old = atomicAdd(&g_count, 1);
        isLast = (old == nblocks - 1);
    }
    __syncthreads();
    if (!isLast) return;

    // ---- last block: deterministic final reduction ----
    __threadfence();
    double a = 0.0;
    for (int i = t; i < nblocks; i += TILE) a += g_partials[i];
    #pragma unroll
    for (int off = 16; off > 0; off >>= 1)
        a += __shfl_down_sync(0xffffffffu, a, off);

    __shared__ double ws2[4];
    if ((t & 31) == 0) ws2[t >> 5] = a;
    __syncthreads();
    if (t == 0) {
        double s = ws2[0] + ws2[1] + ws2[2] + ws2[3];
        out[0] = (float)(s * LN2_D / (double)n);   // ln2 hoisted out of the whole sum
        g_count = 0;                               // reset for next graph replay
    }
}

extern "C" void kernel_launch(void* const* d_in, const int* in_sizes, int n_in,
                              void* d_out, int out_size) {
    const float* logits   = (const float*)d_in[0];
    const int*   rankings = (const int*)d_in[1];
    int n  = in_sizes[0];
    int nt = (n + TILE - 1) / TILE;          // 64 for N=8192
    int nblocks = nt * (nt + 1) / 2;         // 2080

    wrnl_kernel<<<nblocks, TILE>>>(logits, rankings, (float*)d_out, n, nt, nblocks);
}